// round 1
// baseline (speedup 1.0000x reference)
#include <cuda_runtime.h>
#include <math.h>

#define B_DIM 64
#define T_DIM 500
#define C_DIM 40
#define LDA   41            // padded pitch: 41 % 32 = 9, gcd(9,32)=1 -> conflict-free columns
#define BT_TOTAL (B_DIM * T_DIM)   // 32000
#define BLOCK_THREADS 128

// scratch for per-(b,t) log-likelihoods (device global: allowed, no allocation)
__device__ float g_ll[BT_TOTAL];

// One CTA per (b,t): load Sigma (40x40) + mu into smem, right-looking Cholesky
// with the rhs (y_true - mu) folded into the trailing update each step, so the
// triangular solve is free (no extra barriers). 2 syncs per k, 80 total.
__global__ __launch_bounds__(BLOCK_THREADS)
void chol_ll_kernel(const float* __restrict__ y_true,
                    const float* __restrict__ y_pred) {
    const int bt  = blockIdx.x;
    const int tid = threadIdx.x;

    __shared__ float A[C_DIM][LDA];
    __shared__ float rhs[C_DIM];
    __shared__ float s_invd, s_z, s_logdet, s_sumsq;

    const float* yp = y_pred + (size_t)bt * (C_DIM * (C_DIM + 1));
    const float* yt = y_true + (size_t)bt * C_DIM;

    // Coalesced load of the 40x41 slice; column 40 is mu -> build rhs.
    for (int idx = tid; idx < C_DIM * (C_DIM + 1); idx += BLOCK_THREADS) {
        int i = idx / (C_DIM + 1);
        int j = idx - i * (C_DIM + 1);
        float v = yp[idx];
        if (j < C_DIM) A[i][j] = v;
        else           rhs[i]  = yt[i] - v;
    }
    if (tid == 0) { s_logdet = 0.0f; s_sumsq = 0.0f; }
    __syncthreads();

    for (int k = 0; k < C_DIM; ++k) {
        // Step 1: pivot sqrt, logdet accum, and z_k = rhs[k]/L[k][k]
        if (tid == 0) {
            float d   = sqrtf(A[k][k]);
            float inv = 1.0f / d;
            s_invd    = inv;
            s_logdet += logf(d);
            float z   = rhs[k] * inv;
            s_z       = z;
            s_sumsq  += z * z;
        }
        __syncthreads();

        // Step 2: scale column k
        float inv = s_invd;
        for (int i = k + 1 + tid; i < C_DIM; i += BLOCK_THREADS)
            A[i][k] *= inv;
        __syncthreads();

        // Step 3: trailing-submatrix rank-1 update + rhs update (fused solve)
        const int n     = C_DIM - k - 1;
        const int total = n * (n + 1) / 2;
        const float z   = s_z;
        for (int p = tid; p < total + n; p += BLOCK_THREADS) {
            if (p < total) {
                // decode flattened lower-triangle index p -> (r, c), c <= r
                int r = (int)((sqrtf(8.0f * (float)p + 1.0f) - 1.0f) * 0.5f);
                while ((r + 1) * (r + 2) / 2 <= p) ++r;   // fp correction
                while (r * (r + 1) / 2 > p)       --r;
                int c = p - r * (r + 1) / 2;
                int i = k + 1 + r;
                int j = k + 1 + c;
                A[i][j] -= A[i][k] * A[j][k];
            } else {
                int i = k + 1 + (p - total);
                rhs[i] -= A[i][k] * z;
            }
        }
        __syncthreads();
    }

    if (tid == 0) {
        const float HALF_C_LOG2PI = 0.5f * 40.0f * 1.83787706640934548356f; // 0.5*C*log(2*pi)
        g_ll[bt] = -0.5f * s_sumsq - s_logdet - HALF_C_LOG2PI;
    }
}

// Deterministic single-CTA reduction: fixed per-thread serial order + fixed tree.
__global__ void reduce_kernel(float* __restrict__ out) {
    __shared__ float sh[1024];
    const int tid = threadIdx.x;
    float s = 0.0f;
    for (int i = tid; i < BT_TOTAL; i += 1024) s += g_ll[i];
    sh[tid] = s;
    __syncthreads();
    for (int o = 512; o > 0; o >>= 1) {
        if (tid < o) sh[tid] += sh[tid + o];
        __syncthreads();
    }
    if (tid == 0) out[0] = -sh[0] / (float)B_DIM;
}

extern "C" void kernel_launch(void* const* d_in, const int* in_sizes, int n_in,
                              void* d_out, int out_size) {
    // y_true has 1.28M elements, y_pred 52.48M; disambiguate by size.
    const float* a = (const float*)d_in[0];
    const float* b = (const float*)d_in[1];
    const float* y_true = a;
    const float* y_pred = b;
    if (in_sizes[0] > in_sizes[1]) { y_true = b; y_pred = a; }

    chol_ll_kernel<<<BT_TOTAL, BLOCK_THREADS>>>(y_true, y_pred);
    reduce_kernel<<<1, 1024>>>((float*)d_out);
}

// round 4
// speedup vs baseline: 4.0121x; 4.0121x over previous
#include <cuda_runtime.h>
#include <math.h>

#define B_DIM 64
#define T_DIM 500
#define C_DIM 40
#define BT_TOTAL (B_DIM * T_DIM)     // 32000
#define ROW_ELEMS (C_DIM + 1)        // 41 floats per row of y_pred slice
#define SLICE_ELEMS (C_DIM * ROW_ELEMS)  // 1640
#define WARPS_PER_CTA 4
#define BLOCK_THREADS (WARPS_PER_CTA * 32)
#define FULL_MASK 0xffffffffu

__device__ float g_ll[BT_TOTAL];
__device__ float g_part[64];

// Warp-per-problem Cholesky + forward solve, fully register-resident.
// Lane l owns rows l and l+32 (r1 valid only for lanes 0..7; other lanes'
// r1 is dead weight that never feeds a shuffle source).
// __launch_bounds__(128, 8): allow up to 128 regs/thread (no spills) while
// keeping 32 resident warps/SM.
__global__ __launch_bounds__(BLOCK_THREADS, 8)
void chol_ll_kernel(const float* __restrict__ y_true,
                    const float* __restrict__ y_pred) {
    const int warp = threadIdx.x >> 5;
    const int lane = threadIdx.x & 31;
    const int bt   = blockIdx.x * WARPS_PER_CTA + warp;

    __shared__ float sm[WARPS_PER_CTA][SLICE_ELEMS];
    float* s = sm[warp];

    // Coalesced stage of the 40x41 y_pred slice into smem.
    const float* yp = y_pred + (size_t)bt * SLICE_ELEMS;
    #pragma unroll
    for (int i = 0; i < SLICE_ELEMS / 32; ++i)
        s[i * 32 + lane] = yp[i * 32 + lane];
    if (lane < (SLICE_ELEMS & 31))
        s[(SLICE_ELEMS & ~31) + lane] = yp[(SLICE_ELEMS & ~31) + lane];
    __syncwarp();

    // Distribute rows into registers. Pitch 41: (41*l + c) % 32 = (9l+c) % 32,
    // gcd(9,32)=1 -> conflict-free LDS per column index c.
    float r0[C_DIM], r1[C_DIM];
    const int base0 = lane * ROW_ELEMS;
    const int base1 = (lane + 32) * ROW_ELEMS;
    const bool has1 = (lane < C_DIM - 32);   // lanes 0..7
    #pragma unroll
    for (int c = 0; c < C_DIM; ++c) {
        r0[c] = s[base0 + c];
        r1[c] = has1 ? s[base1 + c] : 0.0f;
    }
    float rhs0 = y_true[(size_t)bt * C_DIM + lane] - s[base0 + C_DIM];
    float rhs1 = has1 ? (y_true[(size_t)bt * C_DIM + lane + 32] - s[base1 + C_DIM])
                      : 0.0f;

    float logdet = 0.0f;   // accumulates sum of log(pivot) = 2 * sum log L_kk
    float sumsq  = 0.0f;

    #pragma unroll
    for (int k = 0; k < C_DIM; ++k) {
        // Broadcast pivot A[k][k] (already fully updated) and rhs[k].
        float piv = (k < 32) ? __shfl_sync(FULL_MASK, r0[k], k)
                             : __shfl_sync(FULL_MASK, r1[k], k - 32);
        float rk  = (k < 32) ? __shfl_sync(FULL_MASK, rhs0, k)
                             : __shfl_sync(FULL_MASK, rhs1, k - 32);
        float inv = rsqrtf(piv);
        logdet += __logf(piv);
        float zk = rk * inv;
        sumsq += zk * zk;

        // Scale column k (rows < k get polluted; never read again).
        r0[k] *= inv;
        r1[k] *= inv;

        // Forward-solve update (unconditional; pollution above row k unread).
        rhs0 -= r0[k] * zk;
        rhs1 -= r1[k] * zk;

        // Trailing rank-1 update: 1 SHFL + 2 FFMA per column, no predication.
        #pragma unroll
        for (int j = k + 1; j < C_DIM; ++j) {
            float ljk = (j < 32) ? __shfl_sync(FULL_MASK, r0[k], j)
                                 : __shfl_sync(FULL_MASK, r1[k], j - 32);
            r0[j] -= r0[k] * ljk;
            r1[j] -= r1[k] * ljk;
        }
    }

    if (lane == 0) {
        const float HALF_C_LOG2PI = 0.5f * 40.0f * 1.83787706640934548356f;
        g_ll[bt] = -0.5f * sumsq - 0.5f * logdet - HALF_C_LOG2PI;
    }
}

// Two-stage deterministic reduction.
__global__ void reduce1_kernel() {
    __shared__ float sh[256];
    const int b   = blockIdx.x;          // 64 blocks, 500 values each
    const int tid = threadIdx.x;
    float sacc = 0.0f;
    for (int i = tid; i < T_DIM; i += 256)
        sacc += g_ll[b * T_DIM + i];
    sh[tid] = sacc;
    __syncthreads();
    for (int o = 128; o > 0; o >>= 1) {
        if (tid < o) sh[tid] += sh[tid + o];
        __syncthreads();
    }
    if (tid == 0) g_part[b] = sh[0];
}

__global__ void reduce2_kernel(float* __restrict__ out) {
    __shared__ float sh[64];
    const int tid = threadIdx.x;
    sh[tid] = g_part[tid];
    __syncthreads();
    for (int o = 32; o > 0; o >>= 1) {
        if (tid < o) sh[tid] += sh[tid + o];
        __syncthreads();
    }
    if (tid == 0) out[0] = -sh[0] / (float)B_DIM;
}

extern "C" void kernel_launch(void* const* d_in, const int* in_sizes, int n_in,
                              void* d_out, int out_size) {
    const float* a = (const float*)d_in[0];
    const float* b = (const float*)d_in[1];
    const float* y_true = a;
    const float* y_pred = b;
    if (in_sizes[0] > in_sizes[1]) { y_true = b; y_pred = a; }

    chol_ll_kernel<<<BT_TOTAL / WARPS_PER_CTA, BLOCK_THREADS>>>(y_true, y_pred);
    reduce1_kernel<<<64, 256>>>();
    reduce2_kernel<<<1, 64>>>((float*)d_out);
}

// round 5
// speedup vs baseline: 6.4397x; 1.6051x over previous
#include <cuda_runtime.h>
#include <math.h>

#define B_DIM 64
#define T_DIM 500
#define C_DIM 40
#define BT_TOTAL (B_DIM * T_DIM)     // 32000
#define ROW_ELEMS (C_DIM + 1)        // 41 floats per row of y_pred slice
#define SLICE_ELEMS (C_DIM * ROW_ELEMS)  // 1640
#define WARPS_PER_CTA 4
#define BLOCK_THREADS (WARPS_PER_CTA * 32)
#define FULL_MASK 0xffffffffu

__device__ float g_ll[BT_TOTAL];
__device__ float g_part[64];

// Warp-per-problem Cholesky + forward solve, fully register-resident.
// Lane l owns rows l and l+32 (r1 meaningful only for lanes 0..7).
// __launch_bounds__(128, 4): 128-reg budget -> ~100 live regs, ZERO spills
// (R4's (128,8) capped at 64 regs and spilled 40 floats/thread -> L1 86%).
__global__ __launch_bounds__(BLOCK_THREADS, 4)
void chol_ll_kernel(const float* __restrict__ y_true,
                    const float* __restrict__ y_pred) {
    const int warp = threadIdx.x >> 5;
    const int lane = threadIdx.x & 31;
    const int bt   = blockIdx.x * WARPS_PER_CTA + warp;

    __shared__ float sm[WARPS_PER_CTA][SLICE_ELEMS];
    float* s = sm[warp];

    // Coalesced stage of the 40x41 y_pred slice into smem.
    const float* yp = y_pred + (size_t)bt * SLICE_ELEMS;
    #pragma unroll
    for (int i = 0; i < SLICE_ELEMS / 32; ++i)
        s[i * 32 + lane] = yp[i * 32 + lane];
    if (lane < (SLICE_ELEMS & 31))
        s[(SLICE_ELEMS & ~31) + lane] = yp[(SLICE_ELEMS & ~31) + lane];
    __syncwarp();

    // Distribute rows into registers. Pitch 41: (41*l + c) % 32 = (9l+c) % 32,
    // gcd(9,32)=1 -> conflict-free LDS per column index c.
    float r0[C_DIM], r1[C_DIM];
    const int base0 = lane * ROW_ELEMS;
    const int base1 = (lane + 32) * ROW_ELEMS;
    const bool has1 = (lane < C_DIM - 32);   // lanes 0..7
    #pragma unroll
    for (int c = 0; c < C_DIM; ++c) {
        r0[c] = s[base0 + c];
        r1[c] = has1 ? s[base1 + c] : 0.0f;
    }
    float rhs0 = y_true[(size_t)bt * C_DIM + lane] - s[base0 + C_DIM];
    float rhs1 = has1 ? (y_true[(size_t)bt * C_DIM + lane + 32] - s[base1 + C_DIM])
                      : 0.0f;

    float logdet  = 0.0f;    // sum over groups of log(prod of 8 pivots)
    float pivprod = 1.0f;    // running product of pivots (groups of 8: <=~1e8, safe)
    float sumsq   = 0.0f;

    #pragma unroll
    for (int k = 0; k < C_DIM; ++k) {
        // Broadcast pivot A[k][k] (already fully updated) and rhs[k].
        float piv = (k < 32) ? __shfl_sync(FULL_MASK, r0[k], k)
                             : __shfl_sync(FULL_MASK, r1[k], k - 32);
        float rk  = (k < 32) ? __shfl_sync(FULL_MASK, rhs0, k)
                             : __shfl_sync(FULL_MASK, rhs1, k - 32);
        float inv = rsqrtf(piv);
        pivprod *= piv;
        if ((k & 7) == 7) { logdet += __logf(pivprod); pivprod = 1.0f; }
        float zk = rk * inv;
        sumsq += zk * zk;

        // Scale column k (rows < k get polluted; never read again).
        r0[k] *= inv;
        r1[k] *= inv;

        // Forward-solve update (unconditional; pollution above row k unread).
        rhs0 -= r0[k] * zk;
        rhs1 -= r1[k] * zk;

        // Trailing rank-1 update: 1 SHFL + 2 FFMA per column, no predication.
        // The shuffles within this loop are mutually independent -> pipeline.
        #pragma unroll
        for (int j = k + 1; j < C_DIM; ++j) {
            float ljk = (j < 32) ? __shfl_sync(FULL_MASK, r0[k], j)
                                 : __shfl_sync(FULL_MASK, r1[k], j - 32);
            r0[j] -= r0[k] * ljk;
            r1[j] -= r1[k] * ljk;
        }
    }

    if (lane == 0) {
        const float HALF_C_LOG2PI = 0.5f * 40.0f * 1.83787706640934548356f;
        g_ll[bt] = -0.5f * sumsq - 0.5f * logdet - HALF_C_LOG2PI;
    }
}

// Two-stage deterministic reduction.
__global__ void reduce1_kernel() {
    __shared__ float sh[256];
    const int b   = blockIdx.x;          // 64 blocks, 500 values each
    const int tid = threadIdx.x;
    float sacc = 0.0f;
    for (int i = tid; i < T_DIM; i += 256)
        sacc += g_ll[b * T_DIM + i];
    sh[tid] = sacc;
    __syncthreads();
    for (int o = 128; o > 0; o >>= 1) {
        if (tid < o) sh[tid] += sh[tid + o];
        __syncthreads();
    }
    if (tid == 0) g_part[b] = sh[0];
}

__global__ void reduce2_kernel(float* __restrict__ out) {
    __shared__ float sh[64];
    const int tid = threadIdx.x;
    sh[tid] = g_part[tid];
    __syncthreads();
    for (int o = 32; o > 0; o >>= 1) {
        if (tid < o) sh[tid] += sh[tid + o];
        __syncthreads();
    }
    if (tid == 0) out[0] = -sh[0] / (float)B_DIM;
}

extern "C" void kernel_launch(void* const* d_in, const int* in_sizes, int n_in,
                              void* d_out, int out_size) {
    const float* a = (const float*)d_in[0];
    const float* b = (const float*)d_in[1];
    const float* y_true = a;
    const float* y_pred = b;
    if (in_sizes[0] > in_sizes[1]) { y_true = b; y_pred = a; }

    chol_ll_kernel<<<BT_TOTAL / WARPS_PER_CTA, BLOCK_THREADS>>>(y_true, y_pred);
    reduce1_kernel<<<64, 256>>>();
    reduce2_kernel<<<1, 64>>>((float*)d_out);
}